// round 9
// baseline (speedup 1.0000x reference)
#include <cuda_runtime.h>
#include <math.h>

#define Bsz 512
#define Tsz 512
#define Dsz 256
#define NC  4           // T-chunks per batch row (proven geometry)
#define CROWS (Tsz/NC)  // 128 rows per chunk

// out = [p (512) | T_event (512x513) | L_t (512x256) | M_t (512)]
#define OFF_TE 512
#define OFF_L  (512 + 512*513)
#define OFF_M  (OFF_L + 512*256)

__device__ __align__(16) float g_qpart[Bsz*NC*Dsz];
__device__ float g_cnt4[Bsz*NC];
__device__ float g_max4[Bsz*NC];
__device__ float g_tmax[Bsz];
__device__ __align__(16) float g_u[Bsz*Dsz];
__device__ __align__(16) float g_ypart[Bsz*NC*Dsz];
__device__ float g_m4[Bsz*NC], g_Z4[Bsz*NC], g_S4[Bsz*NC];
__device__ int g_sem1[Bsz];   // zero-init; reset by trailing CTA each run
__device__ int g_sem2[Bsz];

// ================= K1: pass-A stream (NC=4) + trailing (q,tmax,Q=q@WQ^T,u=Q@WK) =================
__global__ void __launch_bounds__(256, 5)
k1(const float* __restrict__ wf, const float* __restrict__ ts,
   const unsigned char* __restrict__ pad,
   const float* __restrict__ WQ, const float* __restrict__ WK) {
    int c = blockIdx.x, b = blockIdx.y;
    int tid = threadIdx.x;
    int warp = tid >> 5, lane = tid & 31;
    int t0 = c * CROWS;

    __shared__ float s_valid[CROWS];
    __shared__ float s_rm[CROWS], s_rc[CROWS];
    __shared__ __align__(16) float s_acc[8*Dsz];
    __shared__ __align__(16) float s_q[Dsz];
    __shared__ __align__(16) float s_Q[Dsz];
    __shared__ int s_last;

    if (tid < CROWS) {
        float v = pad[b*Tsz + t0 + tid] ? 0.f : 1.f;
        s_valid[tid] = v;
        float tv = ts[b*Tsz + t0 + tid];
        s_rm[tid] = (v > 0.f) ? tv : -3.0e38f;
        s_rc[tid] = v;
    }
    __syncthreads();
    for (int s = CROWS/2; s > 0; s >>= 1) {
        if (tid < s) {
            s_rm[tid] = fmaxf(s_rm[tid], s_rm[tid+s]);
            s_rc[tid] += s_rc[tid+s];
        }
        __syncthreads();
    }

    // ---- stream chunk: warp-per-row, 2 rows in flight (proven loop) ----
    const float4* wf4 = (const float4*)(wf + (size_t)b*Tsz*Dsz + (size_t)t0*Dsz);
    {
        float4 A = make_float4(0.f,0.f,0.f,0.f);
        float4 B = make_float4(0.f,0.f,0.f,0.f);
        #pragma unroll 4
        for (int t = warp*2; t < CROWS; t += 16) {
            float4 wa0 = wf4[t*64 + lane];
            float4 wb0 = wf4[t*64 + 32 + lane];
            float4 wa1 = wf4[(t+1)*64 + lane];
            float4 wb1 = wf4[(t+1)*64 + 32 + lane];
            float v0 = s_valid[t], v1 = s_valid[t+1];
            A.x = fmaf(wa0.x, v0, fmaf(wa1.x, v1, A.x));
            A.y = fmaf(wa0.y, v0, fmaf(wa1.y, v1, A.y));
            A.z = fmaf(wa0.z, v0, fmaf(wa1.z, v1, A.z));
            A.w = fmaf(wa0.w, v0, fmaf(wa1.w, v1, A.w));
            B.x = fmaf(wb0.x, v0, fmaf(wb1.x, v1, B.x));
            B.y = fmaf(wb0.y, v0, fmaf(wb1.y, v1, B.y));
            B.z = fmaf(wb0.z, v0, fmaf(wb1.z, v1, B.z));
            B.w = fmaf(wb0.w, v0, fmaf(wb1.w, v1, B.w));
        }
        float4* sa4 = (float4*)s_acc;
        sa4[warp*64 + lane]      = A;
        sa4[warp*64 + 32 + lane] = B;
    }
    __syncthreads();

    int bc = b*NC + c;
    {
        float q = 0.f;
        #pragma unroll
        for (int w = 0; w < 8; w++) q += s_acc[w*Dsz + tid];
        g_qpart[(size_t)bc*Dsz + tid] = q;
    }
    if (tid == 0) { g_max4[bc] = s_rm[0]; g_cnt4[bc] = s_rc[0]; }

    // ---- trailing-CTA election ----
    __threadfence();
    if (tid == 0) s_last = (atomicAdd(&g_sem1[b], 1) == NC - 1) ? 1 : 0;
    __syncthreads();
    if (!s_last) return;

    {
        float q = 0.f, cnt = 0.f, mx = -3.0e38f;
        #pragma unroll
        for (int cc = 0; cc < NC; cc++) {
            q   += g_qpart[(size_t)(b*NC + cc)*Dsz + tid];
            cnt += g_cnt4[b*NC + cc];
            mx   = fmaxf(mx, g_max4[b*NC + cc]);
        }
        s_q[tid] = q / fmaxf(cnt, 1.f);
        if (tid == 0) g_tmax[b] = mx;
    }
    __syncthreads();

    // Q[e] = sum_d q[d]*WQ[e,d] — warp per row, 2 rows in flight (low reg peak)
    {
        const float4* q4 = (const float4*)s_q;
        float4 qA = q4[lane*2], qB = q4[lane*2 + 1];
        #pragma unroll 2
        for (int i = 0; i < 32; i += 2) {
            int e0 = warp*32 + i, e1 = e0 + 1;
            const float4* wr0 = (const float4*)(WQ + (size_t)e0*Dsz);
            const float4* wr1 = (const float4*)(WQ + (size_t)e1*Dsz);
            float4 w0A = wr0[lane*2], w0B = wr0[lane*2+1];
            float4 w1A = wr1[lane*2], w1B = wr1[lane*2+1];
            float d0 = w0A.x*qA.x + w0A.y*qA.y + w0A.z*qA.z + w0A.w*qA.w
                     + w0B.x*qB.x + w0B.y*qB.y + w0B.z*qB.z + w0B.w*qB.w;
            float d1 = w1A.x*qA.x + w1A.y*qA.y + w1A.z*qA.z + w1A.w*qA.w
                     + w1B.x*qB.x + w1B.y*qB.y + w1B.z*qB.z + w1B.w*qB.w;
            #pragma unroll
            for (int o = 16; o > 0; o >>= 1) {
                d0 += __shfl_xor_sync(0xffffffffu, d0, o);
                d1 += __shfl_xor_sync(0xffffffffu, d1, o);
            }
            if (lane == 0) { s_Q[e0] = d0; s_Q[e1] = d1; }
        }
    }
    __syncthreads();

    // u[d2] = sum_e Q[e]*WK[e,d2] — threads over d2 (coalesced)
    {
        float a = 0.f;
        const float* Wp = WK + tid;
        #pragma unroll 8
        for (int e = 0; e < Dsz; e++)
            a = fmaf(s_Q[e], __ldg(Wp + (size_t)e*Dsz), a);
        g_u[(size_t)b*Dsz + tid] = a;
    }
    if (tid == 0) g_sem1[b] = 0;   // reset for next graph replay
}

// ================= K3: pass-B stream (NC=4) + trailing (combine, L=y@WV^T, epilogue) =================
__global__ void __launch_bounds__(256, 5)
k3(const float* __restrict__ wf, const float* __restrict__ ts,
   const unsigned char* __restrict__ pad,
   const float* __restrict__ WV, const float* __restrict__ prevL,
   const float* __restrict__ prevM, const float* __restrict__ clsw,
   const float* __restrict__ clsb, float* __restrict__ out) {
    int c = blockIdx.x, b = blockIdx.y;
    int tid = threadIdx.x;
    int warp = tid >> 5, lane = tid & 31;
    int t0 = c * CROWS;

    __shared__ float s_lam[CROWS];
    __shared__ float s_valid[CROWS];
    __shared__ float s_m[8], s_Z[8], s_S[8];
    __shared__ __align__(16) float s_yp[8*Dsz];
    __shared__ __align__(16) float s_yf[Dsz];
    __shared__ __align__(16) float s_L[Dsz];
    __shared__ float s_w1[8], s_w2[8];
    __shared__ int s_last;

    float tmaxv = g_tmax[b];
    if (tid < CROWS) {
        float v = pad[b*Tsz + t0 + tid] ? 0.f : 1.f;
        float dt = fmaxf(tmaxv - ts[b*Tsz + t0 + tid], 0.f) * (1.f/86400.f);
        s_lam[tid] = __expf(-0.5f*dt) * v;
        s_valid[tid] = v;
    }
    __syncthreads();

    const float4* u4 = (const float4*)(g_u + (size_t)b*Dsz);
    float4 ua = u4[lane], ub = u4[lane + 32];
    const float4* wf4 = (const float4*)(wf + (size_t)b*Tsz*Dsz + (size_t)t0*Dsz);

    float m = -3.0e38f, Z = 0.f, S = 0.f;
    float4 ya = make_float4(0.f,0.f,0.f,0.f);
    float4 yb = make_float4(0.f,0.f,0.f,0.f);

    #pragma unroll 2
    for (int t = warp*2; t < CROWS; t += 16) {
        float4 wa0 = wf4[t*64 + lane];
        float4 wb0 = wf4[t*64 + 32 + lane];
        float4 wa1 = wf4[(t+1)*64 + lane];
        float4 wb1 = wf4[(t+1)*64 + 32 + lane];
        float d0 = wa0.x*ua.x + wa0.y*ua.y + wa0.z*ua.z + wa0.w*ua.w
                 + wb0.x*ub.x + wb0.y*ub.y + wb0.z*ub.z + wb0.w*ub.w;
        float d1 = wa1.x*ua.x + wa1.y*ua.y + wa1.z*ua.z + wa1.w*ua.w
                 + wb1.x*ub.x + wb1.y*ub.y + wb1.z*ub.z + wb1.w*ub.w;
        #pragma unroll
        for (int o = 16; o > 0; o >>= 1) {
            d0 += __shfl_xor_sync(0xffffffffu, d0, o);
            d1 += __shfl_xor_sync(0xffffffffu, d1, o);
        }
        if (s_valid[t] != 0.f) {
            float s  = d0 * 0.0625f;
            float nm = fmaxf(m, s);
            float sc = __expf(m - nm);
            float e  = __expf(s - nm);
            float g  = s_lam[t] * e;
            Z = Z*sc + e;  S = S*sc + g;
            ya.x = fmaf(ya.x, sc, g*wa0.x); ya.y = fmaf(ya.y, sc, g*wa0.y);
            ya.z = fmaf(ya.z, sc, g*wa0.z); ya.w = fmaf(ya.w, sc, g*wa0.w);
            yb.x = fmaf(yb.x, sc, g*wb0.x); yb.y = fmaf(yb.y, sc, g*wb0.y);
            yb.z = fmaf(yb.z, sc, g*wb0.z); yb.w = fmaf(yb.w, sc, g*wb0.w);
            m = nm;
        }
        if (s_valid[t+1] != 0.f) {
            float s  = d1 * 0.0625f;
            float nm = fmaxf(m, s);
            float sc = __expf(m - nm);
            float e  = __expf(s - nm);
            float g  = s_lam[t+1] * e;
            Z = Z*sc + e;  S = S*sc + g;
            ya.x = fmaf(ya.x, sc, g*wa1.x); ya.y = fmaf(ya.y, sc, g*wa1.y);
            ya.z = fmaf(ya.z, sc, g*wa1.z); ya.w = fmaf(ya.w, sc, g*wa1.w);
            yb.x = fmaf(yb.x, sc, g*wb1.x); yb.y = fmaf(yb.y, sc, g*wb1.y);
            yb.z = fmaf(yb.z, sc, g*wb1.z); yb.w = fmaf(yb.w, sc, g*wb1.w);
            m = nm;
        }
    }

    if (lane == 0) s_m[warp] = m;
    __syncthreads();
    float M = s_m[0];
    #pragma unroll
    for (int w = 1; w < 8; w++) M = fmaxf(M, s_m[w]);
    float scw = __expf(m - M);
    if (lane == 0) { s_Z[warp] = Z*scw; s_S[warp] = S*scw; }
    {
        float4* syp4 = (float4*)s_yp;
        syp4[warp*64 + lane]      = make_float4(ya.x*scw, ya.y*scw, ya.z*scw, ya.w*scw);
        syp4[warp*64 + 32 + lane] = make_float4(yb.x*scw, yb.y*scw, yb.z*scw, yb.w*scw);
    }
    __syncthreads();

    int bc = b*NC + c;
    {
        float yv = 0.f;
        #pragma unroll
        for (int w = 0; w < 8; w++) yv += s_yp[w*Dsz + tid];
        g_ypart[(size_t)bc*Dsz + tid] = yv;
    }
    if (tid == 0) {
        float Zt = 0.f, St = 0.f;
        #pragma unroll
        for (int w = 0; w < 8; w++) { Zt += s_Z[w]; St += s_S[w]; }
        g_m4[bc] = M; g_Z4[bc] = Zt; g_S4[bc] = St;
    }

    // ---- trailing-CTA election ----
    __threadfence();
    if (tid == 0) s_last = (atomicAdd(&g_sem2[b], 1) == NC - 1) ? 1 : 0;
    __syncthreads();
    if (!s_last) return;

    // combine split softmax across chunks
    {
        float Mg = -3.0e38f;
        #pragma unroll
        for (int cc = 0; cc < NC; cc++) Mg = fmaxf(Mg, g_m4[b*NC + cc]);
        float Zt = 0.f, St = 0.f, yv = 0.f;
        #pragma unroll
        for (int cc = 0; cc < NC; cc++) {
            float sc = __expf(g_m4[b*NC + cc] - Mg);
            Zt += g_Z4[b*NC + cc] * sc;
            St += g_S4[b*NC + cc] * sc;
            yv += g_ypart[(size_t)(b*NC + cc)*Dsz + tid] * sc;
        }
        float denom = St + 1e-8f*Zt;
        float inv = denom > 0.f ? 1.f/denom : 0.f;
        s_yf[tid] = yv * inv;
    }
    __syncthreads();

    // L = y @ WV^T — warp per row, 2 rows in flight (low reg peak)
    {
        const float4* y4 = (const float4*)s_yf;
        float4 yA = y4[lane*2], yB = y4[lane*2 + 1];
        #pragma unroll 2
        for (int i = 0; i < 32; i += 2) {
            int e0 = warp*32 + i, e1 = e0 + 1;
            const float4* wr0 = (const float4*)(WV + (size_t)e0*Dsz);
            const float4* wr1 = (const float4*)(WV + (size_t)e1*Dsz);
            float4 w0A = wr0[lane*2], w0B = wr0[lane*2+1];
            float4 w1A = wr1[lane*2], w1B = wr1[lane*2+1];
            float d0 = w0A.x*yA.x + w0A.y*yA.y + w0A.z*yA.z + w0A.w*yA.w
                     + w0B.x*yB.x + w0B.y*yB.y + w0B.z*yB.z + w0B.w*yB.w;
            float d1 = w1A.x*yA.x + w1A.y*yA.y + w1A.z*yA.z + w1A.w*yA.w
                     + w1B.x*yB.x + w1B.y*yB.y + w1B.z*yB.z + w1B.w*yB.w;
            #pragma unroll
            for (int o = 16; o > 0; o >>= 1) {
                d0 += __shfl_xor_sync(0xffffffffu, d0, o);
                d1 += __shfl_xor_sync(0xffffffffu, d1, o);
            }
            if (lane == 0) { s_L[e0] = d0; s_L[e1] = d1; }
        }
    }
    __syncthreads();

    // epilogue
    {
        float L  = s_L[tid];
        float dl = L - prevL[(size_t)b*Dsz + tid];
        float r1 = dl*dl;
        float r2 = fmaf(L, clsw[tid], dl*clsw[Dsz + tid]);
        #pragma unroll
        for (int o = 16; o > 0; o >>= 1) {
            r1 += __shfl_xor_sync(0xffffffffu, r1, o);
            r2 += __shfl_xor_sync(0xffffffffu, r2, o);
        }
        if (lane == 0) { s_w1[warp] = r1; s_w2[warp] = r2; }
        __syncthreads();
        size_t te = (size_t)OFF_TE + (size_t)b*513;
        out[te + tid]       = L;
        out[te + 256 + tid] = dl;
        out[OFF_L + (size_t)b*Dsz + tid] = L;
        if (tid == 0) {
            float R1 = 0.f, R2 = 0.f;
            #pragma unroll
            for (int w = 0; w < 8; w++) { R1 += s_w1[w]; R2 += s_w2[w]; }
            float Mt = 0.9f*prevM[b] + 0.1f*sqrtf(R1);
            out[OFF_M + b] = Mt;
            out[te + 512]  = Mt;
            out[b] = R2 + Mt*clsw[2*Dsz] + clsb[0];
            g_sem2[b] = 0;   // reset for next graph replay
        }
    }
}

extern "C" void kernel_launch(void* const* d_in, const int* in_sizes, int n_in,
                              void* d_out, int out_size) {
    const float*         wf    = (const float*)d_in[0];
    const float*         ts    = (const float*)d_in[1];
    const float*         prevL = (const float*)d_in[2];
    const float*         prevM = (const float*)d_in[3];
    const unsigned char* pad   = (const unsigned char*)d_in[4];
    const float*         WQ    = (const float*)d_in[5];
    const float*         WK    = (const float*)d_in[6];
    const float*         WV    = (const float*)d_in[7];
    const float*         clsw  = (const float*)d_in[8];
    const float*         clsb  = (const float*)d_in[9];
    float* out = (float*)d_out;

    k1<<<dim3(NC, Bsz), 256>>>(wf, ts, pad, WQ, WK);
    k3<<<dim3(NC, Bsz), 256>>>(wf, ts, pad, WV, prevL, prevM, clsw, clsb, out);
}

// round 10
// speedup vs baseline: 1.0270x; 1.0270x over previous
#include <cuda_runtime.h>
#include <math.h>

#define Bsz 512
#define Tsz 512
#define Dsz 256
#define NC  4           // T-chunks per batch row
#define CROWS (Tsz/NC)  // 128 rows per chunk

// out = [p (512) | T_event (512x513) | L_t (512x256) | M_t (512)]
#define OFF_TE 512
#define OFF_L  (512 + 512*513)
#define OFF_M  (OFF_L + 512*256)

__device__ __align__(16) float g_qpart[Bsz*NC*Dsz];
__device__ float g_cnt4[Bsz*NC];
__device__ float g_max4[Bsz*NC];
__device__ float g_tmax[Bsz];
__device__ __align__(16) float g_u[Bsz*Dsz];
__device__ __align__(16) float g_ypart[Bsz*NC*Dsz];
__device__ float g_m4[Bsz*NC], g_Z4[Bsz*NC], g_S4[Bsz*NC];

// ---------------- K1: pass A partials (grid: NC x Bsz) — proven R5 code ----------------
__global__ void __launch_bounds__(256)
k1a(const float* __restrict__ wf, const float* __restrict__ ts,
    const unsigned char* __restrict__ pad) {
    int c = blockIdx.x, b = blockIdx.y;
    int tid = threadIdx.x;
    int warp = tid >> 5, lane = tid & 31;
    int t0 = c * CROWS;

    __shared__ float s_valid[CROWS];
    __shared__ float s_rm[CROWS], s_rc[CROWS];
    __shared__ __align__(16) float s_acc[8*Dsz];

    if (tid < CROWS) {
        float v = pad[b*Tsz + t0 + tid] ? 0.f : 1.f;
        s_valid[tid] = v;
        float tv = ts[b*Tsz + t0 + tid];
        s_rm[tid] = (v > 0.f) ? tv : -3.0e38f;
        s_rc[tid] = v;
    }
    __syncthreads();
    for (int s = CROWS/2; s > 0; s >>= 1) {
        if (tid < s) {
            s_rm[tid] = fmaxf(s_rm[tid], s_rm[tid+s]);
            s_rc[tid] += s_rc[tid+s];
        }
        __syncthreads();
    }

    const float4* wf4 = (const float4*)(wf + (size_t)b*Tsz*Dsz + (size_t)t0*Dsz);
    {
        float4 A = make_float4(0.f,0.f,0.f,0.f);
        float4 B = make_float4(0.f,0.f,0.f,0.f);
        #pragma unroll 4
        for (int t = warp*2; t < CROWS; t += 16) {
            float4 wa0 = wf4[t*64 + lane];
            float4 wb0 = wf4[t*64 + 32 + lane];
            float4 wa1 = wf4[(t+1)*64 + lane];
            float4 wb1 = wf4[(t+1)*64 + 32 + lane];
            float v0 = s_valid[t], v1 = s_valid[t+1];
            A.x = fmaf(wa0.x, v0, fmaf(wa1.x, v1, A.x));
            A.y = fmaf(wa0.y, v0, fmaf(wa1.y, v1, A.y));
            A.z = fmaf(wa0.z, v0, fmaf(wa1.z, v1, A.z));
            A.w = fmaf(wa0.w, v0, fmaf(wa1.w, v1, A.w));
            B.x = fmaf(wb0.x, v0, fmaf(wb1.x, v1, B.x));
            B.y = fmaf(wb0.y, v0, fmaf(wb1.y, v1, B.y));
            B.z = fmaf(wb0.z, v0, fmaf(wb1.z, v1, B.z));
            B.w = fmaf(wb0.w, v0, fmaf(wb1.w, v1, B.w));
        }
        float4* sa4 = (float4*)s_acc;
        sa4[warp*64 + lane]      = A;
        sa4[warp*64 + 32 + lane] = B;
    }
    __syncthreads();

    int bc = b*NC + c;
    {
        float q = 0.f;
        #pragma unroll
        for (int w = 0; w < 8; w++) q += s_acc[w*Dsz + tid];
        g_qpart[(size_t)bc*Dsz + tid] = q;
    }
    if (tid == 0) { g_max4[bc] = s_rm[0]; g_cnt4[bc] = s_rc[0]; }
}

// ---------------- K2: reduce q, tmax; Q=q@WQ^T; u=Q@WK (grid 512, 1 b per block) ----------------
__global__ void __launch_bounds__(256)
k_qu(const float* __restrict__ WQ, const float* __restrict__ WK) {
    int b = blockIdx.x, tid = threadIdx.x;
    int warp = tid >> 5, lane = tid & 31;
    __shared__ __align__(16) float s_q[Dsz];
    __shared__ __align__(16) float s_Q[Dsz];

    {
        float q = 0.f, cnt = 0.f, mx = -3.0e38f;
        #pragma unroll
        for (int cc = 0; cc < NC; cc++) {
            q   += g_qpart[(size_t)(b*NC + cc)*Dsz + tid];
            cnt += g_cnt4[b*NC + cc];
            mx   = fmaxf(mx, g_max4[b*NC + cc]);
        }
        s_q[tid] = q / fmaxf(cnt, 1.f);
        if (tid == 0) g_tmax[b] = mx;
    }
    __syncthreads();

    // Stage 1: Q[e] = sum_d q[d]*WQ[e,d] — warp per row, 4 rows in flight
    {
        const float4* q4 = (const float4*)s_q;
        float4 qA = q4[lane*2], qB = q4[lane*2 + 1];
        #pragma unroll 2
        for (int i = 0; i < 32; i += 4) {
            float4 wA[4], wB[4];
            #pragma unroll
            for (int j = 0; j < 4; j++) {
                const float4* wr = (const float4*)(WQ + (size_t)(warp*32 + i + j)*Dsz);
                wA[j] = wr[lane*2]; wB[j] = wr[lane*2+1];
            }
            float d[4];
            #pragma unroll
            for (int j = 0; j < 4; j++)
                d[j] = wA[j].x*qA.x + wA[j].y*qA.y + wA[j].z*qA.z + wA[j].w*qA.w
                     + wB[j].x*qB.x + wB[j].y*qB.y + wB[j].z*qB.z + wB[j].w*qB.w;
            #pragma unroll
            for (int o = 16; o > 0; o >>= 1) {
                #pragma unroll
                for (int k = 0; k < 4; k++) d[k] += __shfl_xor_sync(0xffffffffu, d[k], o);
            }
            if (lane == 0) {
                #pragma unroll
                for (int j = 0; j < 4; j++) s_Q[warp*32 + i + j] = d[j];
            }
        }
    }
    __syncthreads();

    // Stage 2: u[d2] = sum_e Q[e]*WK[e,d2] — threads over d2 (coalesced)
    {
        float a = 0.f;
        const float* Wp = WK + tid;
        #pragma unroll 8
        for (int e = 0; e < Dsz; e++)
            a = fmaf(s_Q[e], __ldg(Wp + (size_t)e*Dsz), a);
        g_u[(size_t)b*Dsz + tid] = a;
    }
}

// ---------------- K3: pass B partials (grid: NC x Bsz) — proven R5 code ----------------
__global__ void __launch_bounds__(256)
k3a(const float* __restrict__ wf, const float* __restrict__ ts,
    const unsigned char* __restrict__ pad) {
    int c = blockIdx.x, b = blockIdx.y;
    int tid = threadIdx.x;
    int warp = tid >> 5, lane = tid & 31;
    int t0 = c * CROWS;

    __shared__ float s_lam[CROWS];
    __shared__ float s_valid[CROWS];
    __shared__ float s_m[8], s_Z[8], s_S[8];
    __shared__ __align__(16) float s_yp[8*Dsz];

    float tmaxv = g_tmax[b];
    if (tid < CROWS) {
        float v = pad[b*Tsz + t0 + tid] ? 0.f : 1.f;
        float dt = fmaxf(tmaxv - ts[b*Tsz + t0 + tid], 0.f) * (1.f/86400.f);
        s_lam[tid] = __expf(-0.5f*dt) * v;
        s_valid[tid] = v;
    }
    __syncthreads();

    const float4* u4 = (const float4*)(g_u + (size_t)b*Dsz);
    float4 ua = u4[lane], ub = u4[lane + 32];
    const float4* wf4 = (const float4*)(wf + (size_t)b*Tsz*Dsz + (size_t)t0*Dsz);

    float m = -3.0e38f, Z = 0.f, S = 0.f;
    float4 ya = make_float4(0.f,0.f,0.f,0.f);
    float4 yb = make_float4(0.f,0.f,0.f,0.f);

    #pragma unroll 2
    for (int t = warp*2; t < CROWS; t += 16) {
        float4 wa0 = wf4[t*64 + lane];
        float4 wb0 = wf4[t*64 + 32 + lane];
        float4 wa1 = wf4[(t+1)*64 + lane];
        float4 wb1 = wf4[(t+1)*64 + 32 + lane];
        float d0 = wa0.x*ua.x + wa0.y*ua.y + wa0.z*ua.z + wa0.w*ua.w
                 + wb0.x*ub.x + wb0.y*ub.y + wb0.z*ub.z + wb0.w*ub.w;
        float d1 = wa1.x*ua.x + wa1.y*ua.y + wa1.z*ua.z + wa1.w*ua.w
                 + wb1.x*ub.x + wb1.y*ub.y + wb1.z*ub.z + wb1.w*ub.w;
        #pragma unroll
        for (int o = 16; o > 0; o >>= 1) {
            d0 += __shfl_xor_sync(0xffffffffu, d0, o);
            d1 += __shfl_xor_sync(0xffffffffu, d1, o);
        }
        if (s_valid[t] != 0.f) {
            float s  = d0 * 0.0625f;
            float nm = fmaxf(m, s);
            float sc = __expf(m - nm);
            float e  = __expf(s - nm);
            float g  = s_lam[t] * e;
            Z = Z*sc + e;  S = S*sc + g;
            ya.x = fmaf(ya.x, sc, g*wa0.x); ya.y = fmaf(ya.y, sc, g*wa0.y);
            ya.z = fmaf(ya.z, sc, g*wa0.z); ya.w = fmaf(ya.w, sc, g*wa0.w);
            yb.x = fmaf(yb.x, sc, g*wb0.x); yb.y = fmaf(yb.y, sc, g*wb0.y);
            yb.z = fmaf(yb.z, sc, g*wb0.z); yb.w = fmaf(yb.w, sc, g*wb0.w);
            m = nm;
        }
        if (s_valid[t+1] != 0.f) {
            float s  = d1 * 0.0625f;
            float nm = fmaxf(m, s);
            float sc = __expf(m - nm);
            float e  = __expf(s - nm);
            float g  = s_lam[t+1] * e;
            Z = Z*sc + e;  S = S*sc + g;
            ya.x = fmaf(ya.x, sc, g*wa1.x); ya.y = fmaf(ya.y, sc, g*wa1.y);
            ya.z = fmaf(ya.z, sc, g*wa1.z); ya.w = fmaf(ya.w, sc, g*wa1.w);
            yb.x = fmaf(yb.x, sc, g*wb1.x); yb.y = fmaf(yb.y, sc, g*wb1.y);
            yb.z = fmaf(yb.z, sc, g*wb1.z); yb.w = fmaf(yb.w, sc, g*wb1.w);
            m = nm;
        }
    }

    if (lane == 0) s_m[warp] = m;
    __syncthreads();
    float M = s_m[0];
    #pragma unroll
    for (int w = 1; w < 8; w++) M = fmaxf(M, s_m[w]);
    float scw = __expf(m - M);
    if (lane == 0) { s_Z[warp] = Z*scw; s_S[warp] = S*scw; }
    {
        float4* syp4 = (float4*)s_yp;
        syp4[warp*64 + lane]      = make_float4(ya.x*scw, ya.y*scw, ya.z*scw, ya.w*scw);
        syp4[warp*64 + 32 + lane] = make_float4(yb.x*scw, yb.y*scw, yb.z*scw, yb.w*scw);
    }
    __syncthreads();

    int bc = b*NC + c;
    {
        float yv = 0.f;
        #pragma unroll
        for (int w = 0; w < 8; w++) yv += s_yp[w*Dsz + tid];
        g_ypart[(size_t)bc*Dsz + tid] = yv;
    }
    if (tid == 0) {
        float Zt = 0.f, St = 0.f;
        #pragma unroll
        for (int w = 0; w < 8; w++) { Zt += s_Z[w]; St += s_S[w]; }
        g_m4[bc] = M; g_Z4[bc] = Zt; g_S4[bc] = St;
    }
}

// ---------------- K4: combine y + L = y@WV^T + epilogue (grid 512, 1 b per block) ----------------
__global__ void __launch_bounds__(256)
k4(const float* __restrict__ WV, const float* __restrict__ prevL,
   const float* __restrict__ prevM, const float* __restrict__ clsw,
   const float* __restrict__ clsb, float* __restrict__ out) {
    int b = blockIdx.x, tid = threadIdx.x;
    int warp = tid >> 5, lane = tid & 31;
    __shared__ __align__(16) float s_yf[Dsz];
    __shared__ __align__(16) float s_L[Dsz];
    __shared__ float s_w1[8], s_w2[8];

    {
        float m0 = g_m4[b*NC+0], m1 = g_m4[b*NC+1], m2 = g_m4[b*NC+2], m3 = g_m4[b*NC+3];
        float M = fmaxf(fmaxf(m0, m1), fmaxf(m2, m3));
        float c0 = __expf(m0 - M), c1 = __expf(m1 - M), c2 = __expf(m2 - M), c3 = __expf(m3 - M);
        float Zt = g_Z4[b*NC+0]*c0 + g_Z4[b*NC+1]*c1 + g_Z4[b*NC+2]*c2 + g_Z4[b*NC+3]*c3;
        float St = g_S4[b*NC+0]*c0 + g_S4[b*NC+1]*c1 + g_S4[b*NC+2]*c2 + g_S4[b*NC+3]*c3;
        float yv = g_ypart[(size_t)(b*NC+0)*Dsz+tid]*c0 + g_ypart[(size_t)(b*NC+1)*Dsz+tid]*c1
                 + g_ypart[(size_t)(b*NC+2)*Dsz+tid]*c2 + g_ypart[(size_t)(b*NC+3)*Dsz+tid]*c3;
        float denom = St + 1e-8f*Zt;
        float inv = denom > 0.f ? 1.f/denom : 0.f;
        s_yf[tid] = yv * inv;
    }
    __syncthreads();

    // GEMM: warp-per-row, 4 rows in flight (8 LDG.128 outstanding)
    {
        const float4* y4 = (const float4*)s_yf;
        float4 yA = y4[lane*2], yB = y4[lane*2 + 1];
        #pragma unroll 2
        for (int i = 0; i < 32; i += 4) {
            float4 wA[4], wB[4];
            #pragma unroll
            for (int j = 0; j < 4; j++) {
                const float4* wr = (const float4*)(WV + (size_t)(warp*32 + i + j)*Dsz);
                wA[j] = wr[lane*2]; wB[j] = wr[lane*2+1];
            }
            float d[4];
            #pragma unroll
            for (int j = 0; j < 4; j++)
                d[j] = wA[j].x*yA.x + wA[j].y*yA.y + wA[j].z*yA.z + wA[j].w*yA.w
                     + wB[j].x*yB.x + wB[j].y*yB.y + wB[j].z*yB.z + wB[j].w*yB.w;
            #pragma unroll
            for (int o = 16; o > 0; o >>= 1) {
                #pragma unroll
                for (int k = 0; k < 4; k++) d[k] += __shfl_xor_sync(0xffffffffu, d[k], o);
            }
            if (lane == 0) {
                #pragma unroll
                for (int j = 0; j < 4; j++) s_L[warp*32 + i + j] = d[j];
            }
        }
    }
    __syncthreads();

    // epilogue
    {
        float L  = s_L[tid];
        float dl = L - prevL[(size_t)b*Dsz + tid];
        float r1 = dl*dl;
        float r2 = fmaf(L, clsw[tid], dl*clsw[Dsz + tid]);
        #pragma unroll
        for (int o = 16; o > 0; o >>= 1) {
            r1 += __shfl_xor_sync(0xffffffffu, r1, o);
            r2 += __shfl_xor_sync(0xffffffffu, r2, o);
        }
        if (lane == 0) { s_w1[warp] = r1; s_w2[warp] = r2; }
        __syncthreads();
        size_t te = (size_t)OFF_TE + (size_t)b*513;
        out[te + tid]       = L;
        out[te + 256 + tid] = dl;
        out[OFF_L + (size_t)b*Dsz + tid] = L;
        if (tid == 0) {
            float R1 = 0.f, R2 = 0.f;
            #pragma unroll
            for (int w = 0; w < 8; w++) { R1 += s_w1[w]; R2 += s_w2[w]; }
            float Mt = 0.9f*prevM[b] + 0.1f*sqrtf(R1);
            out[OFF_M + b] = Mt;
            out[te + 512]  = Mt;
            out[b] = R2 + Mt*clsw[2*Dsz] + clsb[0];
        }
    }
}

extern "C" void kernel_launch(void* const* d_in, const int* in_sizes, int n_in,
                              void* d_out, int out_size) {
    const float*         wf    = (const float*)d_in[0];
    const float*         ts    = (const float*)d_in[1];
    const float*         prevL = (const float*)d_in[2];
    const float*         prevM = (const float*)d_in[3];
    const unsigned char* pad   = (const unsigned char*)d_in[4];
    const float*         WQ    = (const float*)d_in[5];
    const float*         WK    = (const float*)d_in[6];
    const float*         WV    = (const float*)d_in[7];
    const float*         clsw  = (const float*)d_in[8];
    const float*         clsb  = (const float*)d_in[9];
    float* out = (float*)d_out;

    k1a <<<dim3(NC, Bsz), 256>>>(wf, ts, pad);
    k_qu<<<Bsz, 256>>>(WQ, WK);
    k3a <<<dim3(NC, Bsz), 256>>>(wf, ts, pad);
    k4  <<<Bsz, 256>>>(WV, prevL, prevM, clsw, clsb, out);
}